// round 17
// baseline (speedup 1.0000x reference)
#include <cuda_runtime.h>
#include <cstdint>

// B=256, N=256. Greedy masked argmax (exact reference semantics: max value,
// tie -> smallest flat index). Keys = fp32 bits; softmax values in (0,1) =>
// positive, < 1.0f => order-monotone uint32, < 2^30.
// Head slot: u64 h = (key << 16) | (~((row<<8)|col) & 0xFFFF); u64 max ==
// lexicographic (max key, min flat index). 0 = dead.
// Segment cache: s_seg[row][s] = packed (key<<32)|~col max over seg s's 16
// cols (8s..8s+7 and 128+8s..8s+7). Entries are exact OR stale-pointing-at-a-
// masked-col (upper bounds): masking col c can only invalidate the entry whose
// recorded col == c. An UNMASKED tree winner is therefore the exact row max.
//
// One CTA per batch, 256 threads:
//   init : 8 warps, per-row argmax -> s_top; per-lane-pair seg maxima -> s_seg.
//   loop : warp 0 champion serial loop; rescans are LANE-LOCAL pops from the
//          seg cache (no REDUX/shfl/ballot funnel; concurrent hits parallel),
//          with lazy seg recompute (4x LDG.128) on stale winners.
//          Warps 1-7 sleep at the barrier.
//   epi  : all 8 warps fused zero+one-hot writeout.

#define NN   256
#define SEGS 16
#define FULL 0xFFFFFFFFu
typedef unsigned long long u64;

__device__ __forceinline__ u64 pairmax(u64 a, u64 b) { return a > b ? a : b; }

__global__ __launch_bounds__(256)
void greedy_perm_kernel(const float* __restrict__ scores, float* __restrict__ out) {
    __shared__ u64 s_seg[NN * SEGS];   // 32KB segment-max cache
    __shared__ u64 s_top[NN];          // packed head per row
    __shared__ int s_perm[NN];

    const int b    = blockIdx.x;
    const int tid  = threadIdx.x;
    const int warp = tid >> 5;
    const int lane = tid & 31;
    const float* base  = scores + (size_t)b * NN * NN;
    float*       obase = out    + (size_t)b * NN * NN;

    // ---------- parallel init: warp w -> rows w*32 .. w*32+31 ----------
    #pragma unroll 1
    for (int rg = 0; rg < 8; rg++) {
        const int row0 = warp * 32 + rg * 4;
        float4 A[4], Bq[4];
        #pragma unroll
        for (int q = 0; q < 4; q++) {
            const float4* rp = (const float4*)(base + (size_t)(row0 + q) * NN);
            A[q]  = __ldg(rp + lane);
            Bq[q] = __ldg(rp + 32 + lane);
        }
        #pragma unroll
        for (int q = 0; q < 4; q++) {
            const int row = row0 + q;
            const int c0 = 4 * lane;
            u64 w[8];
            w[0] = ((u64)__float_as_uint(A[q].x)  << 32) | (unsigned)~(c0 + 0);
            w[1] = ((u64)__float_as_uint(A[q].y)  << 32) | (unsigned)~(c0 + 1);
            w[2] = ((u64)__float_as_uint(A[q].z)  << 32) | (unsigned)~(c0 + 2);
            w[3] = ((u64)__float_as_uint(A[q].w)  << 32) | (unsigned)~(c0 + 3);
            w[4] = ((u64)__float_as_uint(Bq[q].x) << 32) | (unsigned)~(128 + c0 + 0);
            w[5] = ((u64)__float_as_uint(Bq[q].y) << 32) | (unsigned)~(128 + c0 + 1);
            w[6] = ((u64)__float_as_uint(Bq[q].z) << 32) | (unsigned)~(128 + c0 + 2);
            w[7] = ((u64)__float_as_uint(Bq[q].w) << 32) | (unsigned)~(128 + c0 + 3);
            u64 loc = pairmax(pairmax(pairmax(w[0], w[1]), pairmax(w[2], w[3])),
                              pairmax(pairmax(w[4], w[5]), pairmax(w[6], w[7])));
            // segment cache: combine lane pair {2t,2t+1} -> seg t (16 cols)
            const u64 other = __shfl_xor_sync(FULL, loc, 1);
            if ((lane & 1) == 0)
                s_seg[row * SEGS + (lane >> 1)] = pairmax(loc, other);
            // head (champion REDUX pair)
            const unsigned k1 = (unsigned)(loc >> 32);
            const unsigned c1 = (~(unsigned)loc) & 255u;
            const unsigned m1 = __reduce_max_sync(FULL, k1);
            const unsigned p1 = __reduce_min_sync(FULL, (k1 == m1) ? c1 : FULL);
            if (lane == 0)
                s_top[row] = ((u64)m1 << 16) |
                             (u64)((~(unsigned)((row << 8) | (int)p1)) & 0xFFFFu);
        }
    }
    __syncthreads();

    if (warp == 0) {
        // ---------- serial greedy loop (champion common path) ----------
        u64 h[8];
        unsigned cmask[8];
        #pragma unroll
        for (int k = 0; k < 8; k++) cmask[k] = 0u;
        #pragma unroll
        for (int j = 0; j < 8; j++) h[j] = s_top[j * 32 + lane];

        #pragma unroll 1
        for (int it = 0; it < NN; it++) {
            u64 loc = pairmax(pairmax(pairmax(h[0], h[1]), pairmax(h[2], h[3])),
                              pairmax(pairmax(h[4], h[5]), pairmax(h[6], h[7])));
            const unsigned bk = (unsigned)(loc >> 16);       // 30-bit key
            const unsigned cp = (~(unsigned)loc) & 0xFFFFu;  // (row<<8)|col

            const unsigned m   = __reduce_max_sync(FULL, bk);
            const unsigned sel = __reduce_min_sync(FULL, (bk == m) ? cp : FULL);
            const int r = (int)(sel >> 8);
            const int c = (int)(sel & 255u);

            if (lane == 0) s_perm[r] = c;

            // mask col c (replicated, static indexing)
            {
                const int w2 = c >> 5; const unsigned bit = 1u << (c & 31);
                #pragma unroll
                for (int k = 0; k < 8; k++) if (k == w2) cmask[k] |= bit;
            }
            // kill assigned row
            if (lane == (r & 31)) {
                const int slot = r >> 5;
                #pragma unroll
                for (int j = 0; j < 8; j++) if (j == slot) h[j] = 0ull;
            }

            if (it == NN - 1) break;

            // rows whose cached argmax col just got masked (champion need mask)
            unsigned need = 0u;
            #pragma unroll
            for (int j = 0; j < 8; j++)
                if ((unsigned)(h[j] >> 16) != 0u &&
                    (((~(unsigned)h[j]) & 255u) == (unsigned)c))
                    need |= (1u << j);

            // LANE-LOCAL rescans from the segment cache (parallel across lanes)
            if (need) {
                #pragma unroll
                for (int j = 0; j < 8; j++) {
                    if (need & (1u << j)) {
                        const int row = j * 32 + lane;
                        const u64* sp = &s_seg[row * SEGS];
                        u64 nh;
                        #pragma unroll 1
                        while (true) {
                            const u64 b0 = pairmax(pairmax(sp[0],  sp[1]),  pairmax(sp[2],  sp[3]));
                            const u64 b1 = pairmax(pairmax(sp[4],  sp[5]),  pairmax(sp[6],  sp[7]));
                            const u64 b2 = pairmax(pairmax(sp[8],  sp[9]),  pairmax(sp[10], sp[11]));
                            const u64 b3 = pairmax(pairmax(sp[12], sp[13]), pairmax(sp[14], sp[15]));
                            const u64 best = pairmax(pairmax(b0, b1), pairmax(b2, b3));
                            const unsigned kk = (unsigned)(best >> 32);
                            const unsigned cc = (~(unsigned)best) & 255u;
                            unsigned mw = 0u;
                            #pragma unroll
                            for (int k = 0; k < 8; k++)
                                if ((int)(cc >> 5) == k) mw = cmask[k];
                            if (((mw >> (cc & 31)) & 1u) == 0u) {
                                nh = ((u64)kk << 16) |
                                     (u64)((~(unsigned)((row << 8) | (int)cc)) & 0xFFFFu);
                                break;
                            }
                            // stale winner: recompute its segment exactly
                            const int s = (int)((cc & 127u) >> 3);
                            const float4* rp4 = (const float4*)(base + (size_t)row * NN);
                            unsigned mlo = 0u, mhi = 0u;
                            #pragma unroll
                            for (int k = 0; k < 4; k++)
                                if ((s >> 2) == k) { mlo = cmask[k]; mhi = cmask[k + 4]; }
                            const int bit0 = 8 * (s & 3);
                            const int cb = 8 * s;
                            u64 t;
                            {
                                const float4 A1 = __ldg(rp4 + 2 * s);
                                const float4 A2 = __ldg(rp4 + 2 * s + 1);
                                u64 w0 = ((u64)(((mlo >> (bit0 + 0)) & 1u) ? 0u : __float_as_uint(A1.x)) << 32) | (unsigned)~(cb + 0);
                                u64 w1 = ((u64)(((mlo >> (bit0 + 1)) & 1u) ? 0u : __float_as_uint(A1.y)) << 32) | (unsigned)~(cb + 1);
                                u64 w2 = ((u64)(((mlo >> (bit0 + 2)) & 1u) ? 0u : __float_as_uint(A1.z)) << 32) | (unsigned)~(cb + 2);
                                u64 w3 = ((u64)(((mlo >> (bit0 + 3)) & 1u) ? 0u : __float_as_uint(A1.w)) << 32) | (unsigned)~(cb + 3);
                                u64 w4 = ((u64)(((mlo >> (bit0 + 4)) & 1u) ? 0u : __float_as_uint(A2.x)) << 32) | (unsigned)~(cb + 4);
                                u64 w5 = ((u64)(((mlo >> (bit0 + 5)) & 1u) ? 0u : __float_as_uint(A2.y)) << 32) | (unsigned)~(cb + 5);
                                u64 w6 = ((u64)(((mlo >> (bit0 + 6)) & 1u) ? 0u : __float_as_uint(A2.z)) << 32) | (unsigned)~(cb + 6);
                                u64 w7 = ((u64)(((mlo >> (bit0 + 7)) & 1u) ? 0u : __float_as_uint(A2.w)) << 32) | (unsigned)~(cb + 7);
                                t = pairmax(pairmax(pairmax(w0, w1), pairmax(w2, w3)),
                                            pairmax(pairmax(w4, w5), pairmax(w6, w7)));
                            }
                            {
                                const float4 B1 = __ldg(rp4 + 32 + 2 * s);
                                const float4 B2 = __ldg(rp4 + 33 + 2 * s);
                                u64 w0 = ((u64)(((mhi >> (bit0 + 0)) & 1u) ? 0u : __float_as_uint(B1.x)) << 32) | (unsigned)~(128 + cb + 0);
                                u64 w1 = ((u64)(((mhi >> (bit0 + 1)) & 1u) ? 0u : __float_as_uint(B1.y)) << 32) | (unsigned)~(128 + cb + 1);
                                u64 w2 = ((u64)(((mhi >> (bit0 + 2)) & 1u) ? 0u : __float_as_uint(B1.z)) << 32) | (unsigned)~(128 + cb + 2);
                                u64 w3 = ((u64)(((mhi >> (bit0 + 3)) & 1u) ? 0u : __float_as_uint(B1.w)) << 32) | (unsigned)~(128 + cb + 3);
                                u64 w4 = ((u64)(((mhi >> (bit0 + 4)) & 1u) ? 0u : __float_as_uint(B2.x)) << 32) | (unsigned)~(128 + cb + 4);
                                u64 w5 = ((u64)(((mhi >> (bit0 + 5)) & 1u) ? 0u : __float_as_uint(B2.y)) << 32) | (unsigned)~(128 + cb + 5);
                                u64 w6 = ((u64)(((mhi >> (bit0 + 6)) & 1u) ? 0u : __float_as_uint(B2.z)) << 32) | (unsigned)~(128 + cb + 6);
                                u64 w7 = ((u64)(((mhi >> (bit0 + 7)) & 1u) ? 0u : __float_as_uint(B2.w)) << 32) | (unsigned)~(128 + cb + 7);
                                t = pairmax(t,
                                            pairmax(pairmax(pairmax(w0, w1), pairmax(w2, w3)),
                                                    pairmax(pairmax(w4, w5), pairmax(w6, w7))));
                            }
                            s_seg[row * SEGS + s] = t;   // now exact; retry tree
                        }
                        h[j] = nh;
                    }
                }
            }
        }
    }
    // warps 1-7 arrive immediately and sleep — zero contention during the loop.
    __syncthreads();

    // ---------- fused writeout: zeros + one-hot, 8 warps, coalesced float4 ----------
    #pragma unroll 1
    for (int rr = 0; rr < 32; rr++) {
        const int row = warp * 32 + rr;
        const int pc = s_perm[row];  // broadcast LDS
        float4* op = (float4*)(obase + (size_t)row * NN);
        #pragma unroll
        for (int hh = 0; hh < 2; hh++) {
            const int f4 = lane + 32 * hh;
            const int c0 = 4 * f4;
            float4 vv;
            vv.x = (pc == c0 + 0) ? 1.0f : 0.0f;
            vv.y = (pc == c0 + 1) ? 1.0f : 0.0f;
            vv.z = (pc == c0 + 2) ? 1.0f : 0.0f;
            vv.w = (pc == c0 + 3) ? 1.0f : 0.0f;
            op[f4] = vv;
        }
    }
}

extern "C" void kernel_launch(void* const* d_in, const int* in_sizes, int n_in,
                              void* d_out, int out_size) {
    const float* soft = (const float*)d_in[0];
    float* out = (float*)d_out;
    greedy_perm_kernel<<<256, 256>>>(soft, out);
}